// round 1
// baseline (speedup 1.0000x reference)
#include <cuda_runtime.h>
#include <cuda_bf16.h>
#include <math_constants.h>

// Problem constants
#define BB 4
#define TT 4096
#define CC 1024
#define HH 64
#define MM (BB * TT)          // 16384 rows

// scale = C^-0.5 ; fold log2(e) so attention uses exp2f
#define SM_SCALE_LOG2E (0.03125f * 1.4426950408889634f)

// Scratch for projected q, k, v  (each 16384 x 64 fp32 = 4 MB)
__device__ float g_q[MM * HH];
__device__ float g_k[MM * HH];
__device__ float g_v[MM * HH];

// ---------------------------------------------------------------------------
// QKV projection: out[mat] = x @ W[mat], block tile 128x64, micro 8x4, KC=32
// ---------------------------------------------------------------------------
#define QKV_TM 128
#define QKV_KC 32

__global__ __launch_bounds__(256) void qkv_kernel(
    const float* __restrict__ x,
    const float* __restrict__ Wq,
    const float* __restrict__ Wk,
    const float* __restrict__ Wv)
{
    __shared__ float xs[QKV_KC][QKV_TM + 4];   // transposed: [k][row]
    __shared__ float ws[QKV_KC][HH + 4];       // [k][col]

    const int mat = blockIdx.y;
    const float* __restrict__ W = (mat == 0) ? Wq : (mat == 1) ? Wk : Wv;
    float* __restrict__ out = (mat == 0) ? g_q : (mat == 1) ? g_k : g_v;

    const int row0 = blockIdx.x * QKV_TM;
    const int t  = threadIdx.x;        // 256 threads: 16x16 grid
    const int ty = t >> 4;             // 0..15 -> 8 rows each
    const int tx = t & 15;             // 0..15 -> 4 cols each

    float acc[8][4];
#pragma unroll
    for (int i = 0; i < 8; i++)
#pragma unroll
        for (int j = 0; j < 4; j++) acc[i][j] = 0.f;

    for (int k0 = 0; k0 < CC; k0 += QKV_KC) {
        // load x tile 128x32 (1024 float4, 4 per thread), store transposed
#pragma unroll
        for (int i = 0; i < 4; i++) {
            int idx = t + i * 256;          // 0..1023
            int r   = idx >> 3;             // 0..127
            int k4  = idx & 7;              // 0..7
            float4 v = *(const float4*)&x[(size_t)(row0 + r) * CC + k0 + k4 * 4];
            xs[k4 * 4 + 0][r] = v.x;
            xs[k4 * 4 + 1][r] = v.y;
            xs[k4 * 4 + 2][r] = v.z;
            xs[k4 * 4 + 3][r] = v.w;
        }
        // load w tile 32x64 (512 float4, 2 per thread)
#pragma unroll
        for (int i = 0; i < 2; i++) {
            int idx = t + i * 256;          // 0..511
            int kk  = idx >> 4;             // 0..31
            int c4  = idx & 15;             // 0..15
            float4 v = *(const float4*)&W[(size_t)(k0 + kk) * HH + c4 * 4];
            *(float4*)&ws[kk][c4 * 4] = v;
        }
        __syncthreads();

#pragma unroll 8
        for (int kk = 0; kk < QKV_KC; kk++) {
            float a[8], b[4];
            *(float4*)&a[0] = *(const float4*)&xs[kk][ty * 8];
            *(float4*)&a[4] = *(const float4*)&xs[kk][ty * 8 + 4];
            *(float4*)&b[0] = *(const float4*)&ws[kk][tx * 4];
#pragma unroll
            for (int i = 0; i < 8; i++)
#pragma unroll
                for (int j = 0; j < 4; j++)
                    acc[i][j] = fmaf(a[i], b[j], acc[i][j]);
        }
        __syncthreads();
    }

    const float sc = (mat == 0) ? SM_SCALE_LOG2E : 1.0f;
#pragma unroll
    for (int i = 0; i < 8; i++) {
        float4 v;
        v.x = acc[i][0] * sc; v.y = acc[i][1] * sc;
        v.z = acc[i][2] * sc; v.w = acc[i][3] * sc;
        *(float4*)&out[(size_t)(row0 + ty * 8 + i) * HH + tx * 4] = v;
    }
}

// ---------------------------------------------------------------------------
// Flash attention (fp32): BQ=BK=64, 256 threads, 4x4 micro-tiles
// smem layout (dynamic): qs[64][68] | ks[64][68] | vs[64][68] | ps[64][68]
// qs/ks/ps transposed ([h-or-key][row]) for LDS.128 operand fetch.
// ---------------------------------------------------------------------------
#define BQ 64
#define BK 64
#define SPITCH 68
#define ATT_SMEM (4 * BK * SPITCH * (int)sizeof(float))   // 69632 B

__global__ __launch_bounds__(256) void attn_kernel(float* __restrict__ out)
{
    extern __shared__ float sm[];
    float* qs = sm;                       // [h][qrow]
    float* ks = sm + 1 * BK * SPITCH;     // [h][krow]
    float* vs = sm + 2 * BK * SPITCH;     // [krow][h]
    float* ps = sm + 3 * BK * SPITCH;     // [krow][qrow]

    const int bid = blockIdx.x;           // 256 blocks
    const int b   = bid & 3;
    const int qt  = 63 - (bid >> 2);      // heavy tiles scheduled first

    const int t  = threadIdx.x;
    const int ty = t >> 4;                // 0..15 -> 4 q-rows
    const int tx = t & 15;                // 0..15 -> 4 cols

    const int qbase = b * TT + qt * BQ;   // first global q row of this tile

    // load Q tile transposed: qs[h][r]
#pragma unroll
    for (int i = 0; i < 4; i++) {
        int idx = t + i * 256;            // 0..1023
        int r   = idx >> 4;               // 0..63
        int h4  = idx & 15;               // 0..15
        float4 v = *(const float4*)&g_q[(size_t)(qbase + r) * HH + h4 * 4];
        qs[(h4 * 4 + 0) * SPITCH + r] = v.x;
        qs[(h4 * 4 + 1) * SPITCH + r] = v.y;
        qs[(h4 * 4 + 2) * SPITCH + r] = v.z;
        qs[(h4 * 4 + 3) * SPITCH + r] = v.w;
    }

    float m[4], l[4], o[4][4];
#pragma unroll
    for (int i = 0; i < 4; i++) {
        m[i] = -1e30f; l[i] = 0.f;
#pragma unroll
        for (int j = 0; j < 4; j++) o[i][j] = 0.f;
    }

    for (int kt = 0; kt <= qt; kt++) {
        __syncthreads();   // previous PV reads done; q load done (first iter)
        const int kbase = b * TT + kt * BK;
        // K tile transposed, V tile natural
#pragma unroll
        for (int i = 0; i < 4; i++) {
            int idx = t + i * 256;
            int r   = idx >> 4;
            int h4  = idx & 15;
            float4 kv = *(const float4*)&g_k[(size_t)(kbase + r) * HH + h4 * 4];
            ks[(h4 * 4 + 0) * SPITCH + r] = kv.x;
            ks[(h4 * 4 + 1) * SPITCH + r] = kv.y;
            ks[(h4 * 4 + 2) * SPITCH + r] = kv.z;
            ks[(h4 * 4 + 3) * SPITCH + r] = kv.w;
            float4 vv = *(const float4*)&g_v[(size_t)(kbase + r) * HH + h4 * 4];
            *(float4*)&vs[r * SPITCH + h4 * 4] = vv;
        }
        __syncthreads();

        // S = Q K^T  (k-dim = H = 64)
        float s[4][4];
#pragma unroll
        for (int i = 0; i < 4; i++)
#pragma unroll
            for (int j = 0; j < 4; j++) s[i][j] = 0.f;

#pragma unroll 8
        for (int h = 0; h < HH; h++) {
            float a[4], bb[4];
            *(float4*)&a[0]  = *(const float4*)&qs[h * SPITCH + ty * 4];
            *(float4*)&bb[0] = *(const float4*)&ks[h * SPITCH + tx * 4];
#pragma unroll
            for (int i = 0; i < 4; i++)
#pragma unroll
                for (int j = 0; j < 4; j++)
                    s[i][j] = fmaf(a[i], bb[j], s[i][j]);
        }

        // causal mask (only on diagonal tile)
        if (kt == qt) {
#pragma unroll
            for (int i = 0; i < 4; i++)
#pragma unroll
                for (int j = 0; j < 4; j++)
                    if (ty * 4 + i < tx * 4 + j) s[i][j] = -1e30f;
        }

        // online softmax per q-row (16 threads per row, in-warp half)
#pragma unroll
        for (int i = 0; i < 4; i++) {
            float mloc = fmaxf(fmaxf(s[i][0], s[i][1]), fmaxf(s[i][2], s[i][3]));
#pragma unroll
            for (int d = 1; d < 16; d <<= 1)
                mloc = fmaxf(mloc, __shfl_xor_sync(0xffffffffu, mloc, d));
            float mnew = fmaxf(m[i], mloc);
            float corr = exp2f(m[i] - mnew);
            l[i] *= corr;
#pragma unroll
            for (int j = 0; j < 4; j++) o[i][j] *= corr;
            float ssum = 0.f;
#pragma unroll
            for (int j = 0; j < 4; j++) {
                float p = exp2f(s[i][j] - mnew);
                s[i][j] = p;
                ssum += p;
            }
#pragma unroll
            for (int d = 1; d < 16; d <<= 1)
                ssum += __shfl_xor_sync(0xffffffffu, ssum, d);
            l[i] += ssum;
            m[i] = mnew;
            // write P transposed: ps[key][qrow]
#pragma unroll
            for (int j = 0; j < 4; j++)
                ps[(tx * 4 + j) * SPITCH + ty * 4 + i] = s[i][j];
        }
        __syncthreads();

        // O += P @ V  (k-dim = keys = 64)
#pragma unroll 8
        for (int kk = 0; kk < BK; kk++) {
            float a[4], bb[4];
            *(float4*)&a[0]  = *(const float4*)&ps[kk * SPITCH + ty * 4];
            *(float4*)&bb[0] = *(const float4*)&vs[kk * SPITCH + tx * 4];
#pragma unroll
            for (int i = 0; i < 4; i++)
#pragma unroll
                for (int j = 0; j < 4; j++)
                    o[i][j] = fmaf(a[i], bb[j], o[i][j]);
        }
    }

    // epilogue: normalize and store
#pragma unroll
    for (int i = 0; i < 4; i++) {
        float inv = 1.0f / l[i];
        float4 v;
        v.x = o[i][0] * inv; v.y = o[i][1] * inv;
        v.z = o[i][2] * inv; v.w = o[i][3] * inv;
        *(float4*)&out[(size_t)(qbase + ty * 4 + i) * HH + tx * 4] = v;
    }
}

// ---------------------------------------------------------------------------
extern "C" void kernel_launch(void* const* d_in, const int* in_sizes, int n_in,
                              void* d_out, int out_size)
{
    const float* x  = (const float*)d_in[0];
    const float* Wq = (const float*)d_in[1];
    const float* Wk = (const float*)d_in[2];
    const float* Wv = (const float*)d_in[3];
    float* out = (float*)d_out;

    static int attr_done = 0;
    (void)attr_done;
    cudaFuncSetAttribute(attn_kernel,
                         cudaFuncAttributeMaxDynamicSharedMemorySize, ATT_SMEM);

    dim3 qkv_grid(MM / QKV_TM, 3);
    qkv_kernel<<<qkv_grid, 256>>>(x, Wq, Wk, Wv);

    attn_kernel<<<BB * (TT / BQ), 256, ATT_SMEM>>>(out);
}

// round 2
// speedup vs baseline: 1.1744x; 1.1744x over previous
#include <cuda_runtime.h>
#include <cuda_bf16.h>
#include <math_constants.h>

// Problem constants
#define BB 4
#define TT 4096
#define CC 1024
#define HH 64
#define MM (BB * TT)          // 16384 rows

// scale = C^-0.5 ; fold log2(e) so attention uses exp2
#define SM_SCALE_LOG2E (0.03125f * 1.4426950408889634f)

// Scratch for projected q, k, v  (each 16384 x 64 fp32 = 4 MB)
__device__ float g_q[MM * HH];
__device__ float g_k[MM * HH];
__device__ float g_v[MM * HH];

__device__ __forceinline__ float fast_ex2(float x) {
    float y;
    asm("ex2.approx.ftz.f32 %0, %1;" : "=f"(y) : "f"(x));
    return y;
}

// ---------------------------------------------------------------------------
// QKV projection: out[mat] = x @ W[mat], block tile 128x64, micro 8x4, KC=32
// (measured ~81% of fp32 FMA peak — unchanged this round)
// ---------------------------------------------------------------------------
#define QKV_TM 128
#define QKV_KC 32

__global__ __launch_bounds__(256) void qkv_kernel(
    const float* __restrict__ x,
    const float* __restrict__ Wq,
    const float* __restrict__ Wk,
    const float* __restrict__ Wv)
{
    __shared__ float xs[QKV_KC][QKV_TM + 4];   // transposed: [k][row]
    __shared__ float ws[QKV_KC][HH + 4];       // [k][col]

    const int mat = blockIdx.y;
    const float* __restrict__ W = (mat == 0) ? Wq : (mat == 1) ? Wk : Wv;
    float* __restrict__ out = (mat == 0) ? g_q : (mat == 1) ? g_k : g_v;

    const int row0 = blockIdx.x * QKV_TM;
    const int t  = threadIdx.x;        // 256 threads: 16x16 grid
    const int ty = t >> 4;             // 0..15 -> 8 rows each
    const int tx = t & 15;             // 0..15 -> 4 cols each

    float acc[8][4];
#pragma unroll
    for (int i = 0; i < 8; i++)
#pragma unroll
        for (int j = 0; j < 4; j++) acc[i][j] = 0.f;

    for (int k0 = 0; k0 < CC; k0 += QKV_KC) {
#pragma unroll
        for (int i = 0; i < 4; i++) {
            int idx = t + i * 256;          // 0..1023
            int r   = idx >> 3;             // 0..127
            int k4  = idx & 7;              // 0..7
            float4 v = *(const float4*)&x[(size_t)(row0 + r) * CC + k0 + k4 * 4];
            xs[k4 * 4 + 0][r] = v.x;
            xs[k4 * 4 + 1][r] = v.y;
            xs[k4 * 4 + 2][r] = v.z;
            xs[k4 * 4 + 3][r] = v.w;
        }
#pragma unroll
        for (int i = 0; i < 2; i++) {
            int idx = t + i * 256;          // 0..511
            int kk  = idx >> 4;             // 0..31
            int c4  = idx & 15;             // 0..15
            float4 v = *(const float4*)&W[(size_t)(k0 + kk) * HH + c4 * 4];
            *(float4*)&ws[kk][c4 * 4] = v;
        }
        __syncthreads();

#pragma unroll 8
        for (int kk = 0; kk < QKV_KC; kk++) {
            float a[8], b[4];
            *(float4*)&a[0] = *(const float4*)&xs[kk][ty * 8];
            *(float4*)&a[4] = *(const float4*)&xs[kk][ty * 8 + 4];
            *(float4*)&b[0] = *(const float4*)&ws[kk][tx * 4];
#pragma unroll
            for (int i = 0; i < 8; i++)
#pragma unroll
                for (int j = 0; j < 4; j++)
                    acc[i][j] = fmaf(a[i], b[j], acc[i][j]);
        }
        __syncthreads();
    }

    const float sc = (mat == 0) ? SM_SCALE_LOG2E : 1.0f;
#pragma unroll
    for (int i = 0; i < 8; i++) {
        float4 v;
        v.x = acc[i][0] * sc; v.y = acc[i][1] * sc;
        v.z = acc[i][2] * sc; v.w = acc[i][3] * sc;
        *(float4*)&out[(size_t)(row0 + ty * 8 + i) * HH + tx * 4] = v;
    }
}

// ---------------------------------------------------------------------------
// Flash attention (fp32): BQ=BK=64, 256 threads, 4x4 micro-tiles.
//
// Scheduling: bid and bid+148 share an SM (slot = bid % 148). Assign
// complementary job ranks so co-resident weights sum to ~const:
//   rank = bid < 148 ? bid : 403 - bid       (ranks s and 255-s pair up)
//   qt   = 63 - (rank >> 2)   -> weight qt+1; pair sums = 64.5 +- 0.5
// Single-CTA SMs (slots 108..147) get light jobs (28..37 units).
// ---------------------------------------------------------------------------
#define BQ 64
#define BK 64
#define SPITCH 68
#define ATT_SMEM (4 * BK * SPITCH * (int)sizeof(float))   // 69632 B

__global__ __launch_bounds__(256) void attn_kernel(float* __restrict__ out)
{
    extern __shared__ float sm[];
    float* qs = sm;                       // [h][qrow]
    float* ks = sm + 1 * BK * SPITCH;     // [h][krow]
    float* vs = sm + 2 * BK * SPITCH;     // [krow][h]
    float* ps = sm + 3 * BK * SPITCH;     // [krow][qrow]

    const int bid  = blockIdx.x;                    // 256 blocks
    const int rank = (bid < 148) ? bid : 403 - bid; // complementary pairing
    const int b    = rank & 3;
    const int qt   = 63 - (rank >> 2);              // weight = qt+1

    const int t  = threadIdx.x;
    const int ty = t >> 4;                // 0..15 -> 4 q-rows
    const int tx = t & 15;                // 0..15 -> 4 cols

    const int qbase = b * TT + qt * BQ;   // first global q row of this tile

    // load Q tile transposed: qs[h][r]
#pragma unroll
    for (int i = 0; i < 4; i++) {
        int idx = t + i * 256;            // 0..1023
        int r   = idx >> 4;               // 0..63
        int h4  = idx & 15;               // 0..15
        float4 v = *(const float4*)&g_q[(size_t)(qbase + r) * HH + h4 * 4];
        qs[(h4 * 4 + 0) * SPITCH + r] = v.x;
        qs[(h4 * 4 + 1) * SPITCH + r] = v.y;
        qs[(h4 * 4 + 2) * SPITCH + r] = v.z;
        qs[(h4 * 4 + 3) * SPITCH + r] = v.w;
    }

    float m[4], l[4], o[4][4];
#pragma unroll
    for (int i = 0; i < 4; i++) {
        m[i] = -1e30f; l[i] = 0.f;
#pragma unroll
        for (int j = 0; j < 4; j++) o[i][j] = 0.f;
    }

    for (int kt = 0; kt <= qt; kt++) {
        __syncthreads();   // previous PV reads done; q load done (first iter)
        const int kbase = b * TT + kt * BK;
        // K tile transposed, V tile natural
#pragma unroll
        for (int i = 0; i < 4; i++) {
            int idx = t + i * 256;
            int r   = idx >> 4;
            int h4  = idx & 15;
            float4 kv = *(const float4*)&g_k[(size_t)(kbase + r) * HH + h4 * 4];
            ks[(h4 * 4 + 0) * SPITCH + r] = kv.x;
            ks[(h4 * 4 + 1) * SPITCH + r] = kv.y;
            ks[(h4 * 4 + 2) * SPITCH + r] = kv.z;
            ks[(h4 * 4 + 3) * SPITCH + r] = kv.w;
            float4 vv = *(const float4*)&g_v[(size_t)(kbase + r) * HH + h4 * 4];
            *(float4*)&vs[r * SPITCH + h4 * 4] = vv;
        }
        __syncthreads();

        // S = Q K^T  (k-dim = H = 64)
        float s[4][4];
#pragma unroll
        for (int i = 0; i < 4; i++)
#pragma unroll
            for (int j = 0; j < 4; j++) s[i][j] = 0.f;

#pragma unroll 8
        for (int h = 0; h < HH; h++) {
            float a[4], bb[4];
            *(float4*)&a[0]  = *(const float4*)&qs[h * SPITCH + ty * 4];
            *(float4*)&bb[0] = *(const float4*)&ks[h * SPITCH + tx * 4];
#pragma unroll
            for (int i = 0; i < 4; i++)
#pragma unroll
                for (int j = 0; j < 4; j++)
                    s[i][j] = fmaf(a[i], bb[j], s[i][j]);
        }

        // causal mask (only on diagonal tile)
        if (kt == qt) {
#pragma unroll
            for (int i = 0; i < 4; i++)
#pragma unroll
                for (int j = 0; j < 4; j++)
                    if (ty * 4 + i < tx * 4 + j) s[i][j] = -1e30f;
        }

        // online softmax per q-row (16 threads per row, in-warp half)
#pragma unroll
        for (int i = 0; i < 4; i++) {
            float mloc = fmaxf(fmaxf(s[i][0], s[i][1]), fmaxf(s[i][2], s[i][3]));
#pragma unroll
            for (int d = 1; d < 16; d <<= 1)
                mloc = fmaxf(mloc, __shfl_xor_sync(0xffffffffu, mloc, d));
            float mnew = fmaxf(m[i], mloc);
            float corr = fast_ex2(m[i] - mnew);
            l[i] *= corr;
#pragma unroll
            for (int j = 0; j < 4; j++) o[i][j] *= corr;
            float ssum = 0.f;
#pragma unroll
            for (int j = 0; j < 4; j++) {
                float p = fast_ex2(s[i][j] - mnew);
                s[i][j] = p;
                ssum += p;
            }
#pragma unroll
            for (int d = 1; d < 16; d <<= 1)
                ssum += __shfl_xor_sync(0xffffffffu, ssum, d);
            l[i] += ssum;
            m[i] = mnew;
            // write P transposed: ps[key][qrow]
#pragma unroll
            for (int j = 0; j < 4; j++)
                ps[(tx * 4 + j) * SPITCH + ty * 4 + i] = s[i][j];
        }
        __syncthreads();

        // O += P @ V  (k-dim = keys = 64)
#pragma unroll 8
        for (int kk = 0; kk < BK; kk++) {
            float a[4], bb[4];
            *(float4*)&a[0]  = *(const float4*)&ps[kk * SPITCH + ty * 4];
            *(float4*)&bb[0] = *(const float4*)&vs[kk * SPITCH + tx * 4];
#pragma unroll
            for (int i = 0; i < 4; i++)
#pragma unroll
                for (int j = 0; j < 4; j++)
                    o[i][j] = fmaf(a[i], bb[j], o[i][j]);
        }
    }

    // epilogue: normalize and store
#pragma unroll
    for (int i = 0; i < 4; i++) {
        float inv = 1.0f / l[i];
        float4 v;
        v.x = o[i][0] * inv; v.y = o[i][1] * inv;
        v.z = o[i][2] * inv; v.w = o[i][3] * inv;
        *(float4*)&out[(size_t)(qbase + ty * 4 + i) * HH + tx * 4] = v;
    }
}

// ---------------------------------------------------------------------------
extern "C" void kernel_launch(void* const* d_in, const int* in_sizes, int n_in,
                              void* d_out, int out_size)
{
    const float* x  = (const float*)d_in[0];
    const float* Wq = (const float*)d_in[1];
    const float* Wk = (const float*)d_in[2];
    const float* Wv = (const float*)d_in[3];
    float* out = (float*)d_out;

    cudaFuncSetAttribute(attn_kernel,
                         cudaFuncAttributeMaxDynamicSharedMemorySize, ATT_SMEM);

    dim3 qkv_grid(MM / QKV_TM, 3);
    qkv_kernel<<<qkv_grid, 256>>>(x, Wq, Wk, Wv);

    attn_kernel<<<BB * (TT / BQ), 256, ATT_SMEM>>>(out);
}

// round 4
// speedup vs baseline: 2.4034x; 2.0466x over previous
#include <cuda_runtime.h>
#include <cuda_bf16.h>
#include <cstdint>

// Problem constants
#define BB 4
#define TT 4096
#define CC 1024
#define HH 64
#define MM (BB * TT)          // 16384 rows

#define SM_SCALE_LOG2E (0.03125f * 1.4426950408889634f)

// ---------------------------------------------------------------------------
// Global scratch
// ---------------------------------------------------------------------------
__device__ uint4  g_qhi4[MM * HH * 2 / 16];   // bf16 [m][64]
__device__ uint4  g_qlo4[MM * HH * 2 / 16];
__device__ uint4  g_khi4[MM * HH * 2 / 16];
__device__ uint4  g_klo4[MM * HH * 2 / 16];
__device__ float4 g_v4  [MM * HH / 4];        // fp32 [m][64]
__device__ uint4  g_vthi4[MM * HH * 2 / 16];  // bf16 [b][h][t]
__device__ uint4  g_vtlo4[MM * HH * 2 / 16];
__device__ float  g_oacc[MM * HH];            // fp32 un-normalized O
__device__ float  g_lacc[MM];                 // fp32 row sums

__device__ __forceinline__ float fast_ex2(float x) {
    float y;
    asm("ex2.approx.ftz.f32 %0, %1;" : "=f"(y) : "f"(x));
    return y;
}
__device__ __forceinline__ uint32_t smem_u32(const void* p) {
    uint32_t a;
    asm("{ .reg .u64 t; cvta.to.shared.u64 t, %1; cvt.u32.u64 %0, t; }"
        : "=r"(a) : "l"(p));
    return a;
}
__device__ __forceinline__ void ldsm4(uint32_t* r, uint32_t addr) {
    asm volatile("ldmatrix.sync.aligned.m8n8.x4.shared.b16 {%0,%1,%2,%3}, [%4];"
                 : "=r"(r[0]), "=r"(r[1]), "=r"(r[2]), "=r"(r[3]) : "r"(addr));
}
__device__ __forceinline__ void mma16816(float* d, const uint32_t* a,
                                         uint32_t b0, uint32_t b1) {
    asm volatile("mma.sync.aligned.m16n8k16.row.col.f32.bf16.bf16.f32 "
                 "{%0,%1,%2,%3}, {%4,%5,%6,%7}, {%8,%9}, {%0,%1,%2,%3};"
                 : "+f"(d[0]), "+f"(d[1]), "+f"(d[2]), "+f"(d[3])
                 : "r"(a[0]), "r"(a[1]), "r"(a[2]), "r"(a[3]), "r"(b0), "r"(b1));
}
__device__ __forceinline__ void cp16(uint32_t dst, const void* src) {
    asm volatile("cp.async.cg.shared.global [%0], [%1], 16;"
                 :: "r"(dst), "l"(src));
}
#define CP_COMMIT() asm volatile("cp.async.commit_group;" ::: "memory")
#define CP_WAIT1()  asm volatile("cp.async.wait_group 1;" ::: "memory")
__device__ __forceinline__ uint32_t packbf2(float lo, float hi) {
    uint32_t r;
    asm("cvt.rn.bf16x2.f32 %0, %1, %2;" : "=r"(r) : "f"(hi), "f"(lo));
    return r;
}
__device__ __forceinline__ float bf16rt(float x) {   // round-trip to bf16
    return __bfloat162float(__float2bfloat16_rn(x));
}

// ---------------------------------------------------------------------------
// QKV projection (fp32 FMA). Emits bf16 hi/lo q (pre-scaled) / k, fp32 v.
// ---------------------------------------------------------------------------
#define QKV_TM 128
#define QKV_KC 32

__global__ __launch_bounds__(256) void qkv_kernel(
    const float* __restrict__ x,
    const float* __restrict__ Wq,
    const float* __restrict__ Wk,
    const float* __restrict__ Wv)
{
    __shared__ float xs[QKV_KC][QKV_TM + 4];
    __shared__ float ws[QKV_KC][HH + 4];

    const int mat = blockIdx.y;
    const float* __restrict__ W = (mat == 0) ? Wq : (mat == 1) ? Wk : Wv;

    const int row0 = blockIdx.x * QKV_TM;
    const int t  = threadIdx.x;
    const int ty = t >> 4;
    const int tx = t & 15;

    float acc[8][4];
#pragma unroll
    for (int i = 0; i < 8; i++)
#pragma unroll
        for (int j = 0; j < 4; j++) acc[i][j] = 0.f;

    for (int k0 = 0; k0 < CC; k0 += QKV_KC) {
#pragma unroll
        for (int i = 0; i < 4; i++) {
            int idx = t + i * 256;
            int r   = idx >> 3;
            int k4  = idx & 7;
            float4 v = *(const float4*)&x[(size_t)(row0 + r) * CC + k0 + k4 * 4];
            xs[k4 * 4 + 0][r] = v.x;
            xs[k4 * 4 + 1][r] = v.y;
            xs[k4 * 4 + 2][r] = v.z;
            xs[k4 * 4 + 3][r] = v.w;
        }
#pragma unroll
        for (int i = 0; i < 2; i++) {
            int idx = t + i * 256;
            int kk  = idx >> 4;
            int c4  = idx & 15;
            float4 v = *(const float4*)&W[(size_t)(k0 + kk) * HH + c4 * 4];
            *(float4*)&ws[kk][c4 * 4] = v;
        }
        __syncthreads();

#pragma unroll 8
        for (int kk = 0; kk < QKV_KC; kk++) {
            float a[8], b[4];
            *(float4*)&a[0] = *(const float4*)&xs[kk][ty * 8];
            *(float4*)&a[4] = *(const float4*)&xs[kk][ty * 8 + 4];
            *(float4*)&b[0] = *(const float4*)&ws[kk][tx * 4];
#pragma unroll
            for (int i = 0; i < 8; i++)
#pragma unroll
                for (int j = 0; j < 4; j++)
                    acc[i][j] = fmaf(a[i], b[j], acc[i][j]);
        }
        __syncthreads();
    }

    if (mat < 2) {
        __nv_bfloat16* ohi = (__nv_bfloat16*)(mat == 0 ? g_qhi4 : g_khi4);
        __nv_bfloat16* olo = (__nv_bfloat16*)(mat == 0 ? g_qlo4 : g_klo4);
        const float sc = (mat == 0) ? SM_SCALE_LOG2E : 1.0f;
#pragma unroll
        for (int i = 0; i < 8; i++) {
            size_t base = (size_t)(row0 + ty * 8 + i) * HH + tx * 4;
            float v[4];
#pragma unroll
            for (int j = 0; j < 4; j++) v[j] = acc[i][j] * sc;
            __nv_bfloat162 h0, h1, l0, l1;
            h0.x = __float2bfloat16_rn(v[0]); h0.y = __float2bfloat16_rn(v[1]);
            h1.x = __float2bfloat16_rn(v[2]); h1.y = __float2bfloat16_rn(v[3]);
            l0.x = __float2bfloat16_rn(v[0] - __bfloat162float(h0.x));
            l0.y = __float2bfloat16_rn(v[1] - __bfloat162float(h0.y));
            l1.x = __float2bfloat16_rn(v[2] - __bfloat162float(h1.x));
            l1.y = __float2bfloat16_rn(v[3] - __bfloat162float(h1.y));
            *(__nv_bfloat162*)&ohi[base]     = h0;
            *(__nv_bfloat162*)&ohi[base + 2] = h1;
            *(__nv_bfloat162*)&olo[base]     = l0;
            *(__nv_bfloat162*)&olo[base + 2] = l1;
        }
    } else {
        float* gv = (float*)g_v4;
#pragma unroll
        for (int i = 0; i < 8; i++) {
            float4 v;
            v.x = acc[i][0]; v.y = acc[i][1]; v.z = acc[i][2]; v.w = acc[i][3];
            *(float4*)&gv[(size_t)(row0 + ty * 8 + i) * HH + tx * 4] = v;
        }
    }
}

// ---------------------------------------------------------------------------
// prep_vt: transpose fp32 v [b*T + t][h] -> bf16 hi/lo vt [b][h][t]
// ---------------------------------------------------------------------------
__global__ __launch_bounds__(256) void prep_vt()
{
    __shared__ float ts[64][65];
    const int b  = blockIdx.y;
    const int t0 = blockIdx.x * 64;
    const int t  = threadIdx.x;
    const float* gv = (const float*)g_v4;
    __nv_bfloat16* vth = (__nv_bfloat16*)g_vthi4;
    __nv_bfloat16* vtl = (__nv_bfloat16*)g_vtlo4;

#pragma unroll
    for (int it = 0; it < 4; it++) {
        int idx = t + it * 256;
        int r   = idx >> 4;
        int h4  = idx & 15;
        float4 v = *(const float4*)&gv[(size_t)(b * TT + t0 + r) * HH + h4 * 4];
        ts[r][h4 * 4 + 0] = v.x;
        ts[r][h4 * 4 + 1] = v.y;
        ts[r][h4 * 4 + 2] = v.z;
        ts[r][h4 * 4 + 3] = v.w;
    }
    __syncthreads();

#pragma unroll
    for (int it = 0; it < 16; it++) {
        int o  = t + it * 256;
        int h  = o >> 6;
        int tt = o & 63;
        float v = ts[tt][h];
        __nv_bfloat16 hb = __float2bfloat16_rn(v);
        size_t oi = (size_t)(b * HH + h) * TT + t0 + tt;
        vth[oi] = hb;
        vtl[oi] = __float2bfloat16_rn(v - __bfloat162float(hb));
    }
}

// ---------------------------------------------------------------------------
// zero accumulators
// ---------------------------------------------------------------------------
__global__ __launch_bounds__(256) void zero_acc()
{
    int i = blockIdx.x * 256 + threadIdx.x;    // 0..262143
    ((float4*)g_oacc)[i] = make_float4(0.f, 0.f, 0.f, 0.f);
    if (i < MM / 4)
        ((float4*)g_lacc)[i] = make_float4(0.f, 0.f, 0.f, 0.f);
}

// ---------------------------------------------------------------------------
// mma.sync flash attention (split-bf16, no-rescale softmax, split-K units).
// Unit = 128 q-rows x 64 keys. Units per (b,qt): 2(qt+1). Total 4224.
// 148 persistent CTAs each take a contiguous ~28.5-unit range; partial (O,l)
// flushed with red.global.add at q-tile boundaries; finalize divides.
// smem: Q hi/lo [128][72]bf16 + 2 stages of {Khi,Klo [64][72], Vthi,Vtlo [64][72]}
// ---------------------------------------------------------------------------
#define UPITCH 144            // 72 bf16 per row
#define OFF_QHI 0
#define OFF_QLO 18432
#define OFF_ST  36864
#define ST_STRIDE 36864
#define ST_KHI 0
#define ST_KLO 9216
#define ST_VHI 18432
#define ST_VLO 27648
#define ATT_SMEM 110592
#define NCTA 148
#define UNITS_PER_B 1056
#define TOTAL_UNITS (BB * UNITS_PER_B)

__device__ __forceinline__ void decode_unit(int u, int& b, int& qt, int& kc) {
    b = u / UNITS_PER_B;
    int r = u - b * UNITS_PER_B;
    int q = (int)((sqrtf(4.f * (float)r + 1.f) - 1.f) * 0.5f);
    while ((q + 1) * (q + 2) <= r) q++;
    while (q * (q + 1) > r) q--;
    qt = q;
    kc = r - q * (q + 1);
}

__global__ __launch_bounds__(256, 1) void attn_kernel()
{
    extern __shared__ char smem[];
    const uint32_t sb = smem_u32(smem);

    const int tid  = threadIdx.x;
    const int wid  = tid >> 5;
    const int lane = tid & 31;

    const __nv_bfloat16* gqh = (const __nv_bfloat16*)g_qhi4;
    const __nv_bfloat16* gql = (const __nv_bfloat16*)g_qlo4;
    const __nv_bfloat16* gkh = (const __nv_bfloat16*)g_khi4;
    const __nv_bfloat16* gkl = (const __nv_bfloat16*)g_klo4;
    const __nv_bfloat16* gvh = (const __nv_bfloat16*)g_vthi4;
    const __nv_bfloat16* gvl = (const __nv_bfloat16*)g_vtlo4;

    const int u0 = (int)(((long long)TOTAL_UNITS * blockIdx.x) / NCTA);
    const int u1 = (int)(((long long)TOTAL_UNITS * (blockIdx.x + 1)) / NCTA);

    // ldmatrix per-lane addressing (constant offsets)
    const int a_row  = wid * 16 + (lane & 7) + ((lane >> 3) & 1) * 8;
    const int a_csel = (lane >> 4) & 1;                 // +8 cols
    const uint32_t qh_base = sb + OFF_QHI + a_row * UPITCH + a_csel * 16;
    const uint32_t ql_base = sb + OFF_QLO + a_row * UPITCH + a_csel * 16;
    const int b_key  = (lane & 7) + ((lane >> 4) & 1) * 8;   // + 16g
    const int b_hsel = (lane >> 3) & 1;                      // +8 cols
    const int v_h    = (lane & 7) + ((lane >> 4) & 1) * 8;   // + 16g
    const int v_ksel = (lane >> 3) & 1;                      // +8 cols

    // prefetch helper: K/V tiles for (b,kc) into stage st
    auto prefetch = [&](int st, int b, int kc) {
        uint32_t so = sb + OFF_ST + st * ST_STRIDE;
        const __nv_bfloat16* kh = gkh + (size_t)(b * TT + kc * 64) * HH;
        const __nv_bfloat16* kl = gkl + (size_t)(b * TT + kc * 64) * HH;
        const __nv_bfloat16* vh = gvh + (size_t)b * HH * TT + (size_t)kc * 64;
        const __nv_bfloat16* vl = gvl + (size_t)b * HH * TT + (size_t)kc * 64;
#pragma unroll
        for (int i = 0; i < 2; i++) {
            int idx = tid + i * 256;       // 0..511
            int r = idx >> 3, c = idx & 7;
            uint32_t d = r * UPITCH + c * 16;
            cp16(so + ST_KHI + d, kh + (size_t)r * HH + c * 8);
            cp16(so + ST_KLO + d, kl + (size_t)r * HH + c * 8);
            cp16(so + ST_VHI + d, vh + (size_t)r * TT + c * 8);
            cp16(so + ST_VLO + d, vl + (size_t)r * TT + c * 8);
        }
    };

    // prologue: prefetch first two units
    {
        int b, qt, kc;
        decode_unit(u0, b, qt, kc);
        prefetch(u0 & 1, b, kc);
        CP_COMMIT();
        if (u0 + 1 < u1) {
            decode_unit(u0 + 1, b, qt, kc);
            prefetch((u0 + 1) & 1, b, kc);
        }
        CP_COMMIT();
    }

    float of[8][4];
    float lsum0 = 0.f, lsum1 = 0.f;
    int cur_b = -1, cur_qt = -1;

    // flush partial (O, l) for q-tile (cb, cq)
    auto flush = [&](int cb, int cq) {
        float s0 = lsum0, s1 = lsum1;
#pragma unroll
        for (int d = 1; d < 4; d <<= 1) {
            s0 += __shfl_xor_sync(0xffffffffu, s0, d);
            s1 += __shfl_xor_sync(0xffffffffu, s1, d);
        }
        int qb = cb * TT + cq * 128;
        int row0 = qb + wid * 16 + (lane >> 2);
        if ((lane & 3) == 0) {
            atomicAdd(&g_lacc[row0], s0);
            atomicAdd(&g_lacc[row0 + 8], s1);
        }
#pragma unroll
        for (int n8 = 0; n8 < 8; n8++) {
            int col = n8 * 8 + (lane & 3) * 2;
            atomicAdd(&g_oacc[(size_t)row0 * HH + col],           of[n8][0]);
            atomicAdd(&g_oacc[(size_t)row0 * HH + col + 1],       of[n8][1]);
            atomicAdd(&g_oacc[(size_t)(row0 + 8) * HH + col],     of[n8][2]);
            atomicAdd(&g_oacc[(size_t)(row0 + 8) * HH + col + 1], of[n8][3]);
        }
    };

    for (int u = u0; u < u1; u++) {
        int b, qt, kc;
        decode_unit(u, b, qt, kc);

        CP_WAIT1();
        __syncthreads();

        if (b != cur_b || qt != cur_qt) {
            if (cur_qt >= 0) flush(cur_b, cur_qt);
#pragma unroll
            for (int i = 0; i < 8; i++)
#pragma unroll
                for (int j = 0; j < 4; j++) of[i][j] = 0.f;
            lsum0 = lsum1 = 0.f;
            // load Q tile hi/lo [128][64] -> smem pitch 72
            const __nv_bfloat16* qh = gqh + (size_t)(b * TT + qt * 128) * HH;
            const __nv_bfloat16* ql = gql + (size_t)(b * TT + qt * 128) * HH;
#pragma unroll
            for (int i = 0; i < 4; i++) {
                int idx = tid + i * 256;   // 0..1023
                int r = idx >> 3, c = idx & 7;
                *(uint4*)(smem + OFF_QHI + r * UPITCH + c * 16) =
                    *(const uint4*)(qh + (size_t)r * HH + c * 8);
                *(uint4*)(smem + OFF_QLO + r * UPITCH + c * 16) =
                    *(const uint4*)(ql + (size_t)r * HH + c * 8);
            }
            __syncthreads();
            cur_b = b; cur_qt = qt;
        }

        const uint32_t so = sb + OFF_ST + (u & 1) * ST_STRIDE;

        // ---- S = Q K^T (split-bf16: hi*hi + lo*hi + hi*lo) ----
        float sf[8][4];
#pragma unroll
        for (int i = 0; i < 8; i++)
#pragma unroll
            for (int j = 0; j < 4; j++) sf[i][j] = 0.f;

#pragma unroll
        for (int ks = 0; ks < 4; ks++) {
            uint32_t ah[4], al[4];
            ldsm4(ah, qh_base + ks * 32);
            ldsm4(al, ql_base + ks * 32);
#pragma unroll
            for (int g = 0; g < 4; g++) {
                uint32_t bh[4], bl[4];
                uint32_t ka = so + (16 * g + b_key) * UPITCH + ks * 32 + b_hsel * 16;
                ldsm4(bh, ka + ST_KHI);
                ldsm4(bl, ka + ST_KLO);
                mma16816(sf[2 * g],     ah, bh[0], bh[1]);
                mma16816(sf[2 * g],     al, bh[0], bh[1]);
                mma16816(sf[2 * g],     ah, bl[0], bl[1]);
                mma16816(sf[2 * g + 1], ah, bh[2], bh[3]);
                mma16816(sf[2 * g + 1], al, bh[2], bh[3]);
                mma16816(sf[2 * g + 1], ah, bl[2], bl[3]);
            }
        }

        // ---- softmax (no rescale) + convert P to bf16 hi/lo A-fragments ----
        const bool needmask = (kc >= 2 * qt);
        const int qrow0 = qt * 128 + wid * 16 + (lane >> 2);
        const int keyb  = kc * 64 + (lane & 3) * 2;
        uint32_t phi[8][2], plo[8][2];
#pragma unroll
        for (int n8 = 0; n8 < 8; n8++) {
            int k0 = keyb + n8 * 8;
            float p0 = fast_ex2(sf[n8][0]);
            float p1 = fast_ex2(sf[n8][1]);
            float p2 = fast_ex2(sf[n8][2]);
            float p3 = fast_ex2(sf[n8][3]);
            if (needmask) {
                if (k0     > qrow0)     p0 = 0.f;
                if (k0 + 1 > qrow0)     p1 = 0.f;
                if (k0     > qrow0 + 8) p2 = 0.f;
                if (k0 + 1 > qrow0 + 8) p3 = 0.f;
            }
            lsum0 += p0 + p1;
            lsum1 += p2 + p3;
            float h0 = bf16rt(p0), h1 = bf16rt(p1), h2 = bf16rt(p2), h3 = bf16rt(p3);
            phi[n8][0] = packbf2(h0, h1);
            phi[n8][1] = packbf2(h2, h3);
            plo[n8][0] = packbf2(p0 - h0, p1 - h1);
            plo[n8][1] = packbf2(p2 - h2, p3 - h3);
        }

        // ---- O += P V (split-bf16: Phi*Vhi + Plo*Vhi + Phi*Vlo) ----
#pragma unroll
        for (int ks = 0; ks < 4; ks++) {
            uint32_t pah[4] = { phi[2 * ks][0], phi[2 * ks][1],
                                phi[2 * ks + 1][0], phi[2 * ks + 1][1] };
            uint32_t pal[4] = { plo[2 * ks][0], plo[2 * ks][1],
                                plo[2 * ks + 1][0], plo[2 * ks + 1][1] };
#pragma unroll
            for (int g = 0; g < 4; g++) {
                uint32_t vh[4], vl[4];
                uint32_t va = so + (16 * g + v_h) * UPITCH + ks * 32 + v_ksel * 16;
                ldsm4(vh, va + ST_VHI);
                ldsm4(vl, va + ST_VLO);
                mma16816(of[2 * g],     pah, vh[0], vh[1]);
                mma16816(of[2 * g],     pal, vh[0], vh[1]);
                mma16816(of[2 * g],     pah, vl[0], vl[1]);
                mma16816(of[2 * g + 1], pah, vh[2], vh[3]);
                mma16816(of[2 * g + 1], pal, vh[2], vh[3]);
                mma16816(of[2 * g + 1], pah, vl[2], vl[3]);
            }
        }

        __syncthreads();
        if (u + 2 < u1) {
            int nb, nqt, nkc;
            decode_unit(u + 2, nb, nqt, nkc);
            prefetch(u & 1, nb, nkc);
        }
        CP_COMMIT();
    }

    flush(cur_b, cur_qt);
}

// ---------------------------------------------------------------------------
// finalize: out = O_acc / l
// ---------------------------------------------------------------------------
__global__ __launch_bounds__(256) void finalize(float* __restrict__ out)
{
    int i = blockIdx.x * 256 + threadIdx.x;    // float4 index, 0..262143
    float4 o = ((const float4*)g_oacc)[i];
    float inv = 1.0f / g_lacc[i >> 4];
    o.x *= inv; o.y *= inv; o.z *= inv; o.w *= inv;
    ((float4*)out)[i] = o;
}

// ---------------------------------------------------------------------------
extern "C" void kernel_launch(void* const* d_in, const int* in_sizes, int n_in,
                              void* d_out, int out_size)
{
    const float* x  = (const float*)d_in[0];
    const float* Wq = (const float*)d_in[1];
    const float* Wk = (const float*)d_in[2];
    const float* Wv = (const float*)d_in[3];
    float* out = (float*)d_out;

    cudaFuncSetAttribute(attn_kernel,
                         cudaFuncAttributeMaxDynamicSharedMemorySize, ATT_SMEM);

    dim3 qkv_grid(MM / QKV_TM, 3);
    qkv_kernel<<<qkv_grid, 256>>>(x, Wq, Wk, Wv);

    dim3 vt_grid(TT / 64, BB);
    prep_vt<<<vt_grid, 256>>>();

    zero_acc<<<MM * HH / 4 / 256, 256>>>();

    attn_kernel<<<NCTA, 256, ATT_SMEM>>>();

    finalize<<<MM * HH / 4 / 256, 256>>>(out);
}

// round 5
// speedup vs baseline: 3.8638x; 1.6076x over previous
#include <cuda_runtime.h>
#include <cuda_bf16.h>
#include <cstdint>

// Problem constants
#define BB 4
#define TT 4096
#define CC 1024
#define HH 64
#define MM (BB * TT)          // 16384 rows

#define SM_SCALE_LOG2E (0.03125f * 1.4426950408889634f)

// ---------------------------------------------------------------------------
// Global scratch
// ---------------------------------------------------------------------------
__device__ uint4  g_qhi4[MM * HH * 2 / 16];   // bf16 [m][64]
__device__ uint4  g_qlo4[MM * HH * 2 / 16];
__device__ uint4  g_khi4[MM * HH * 2 / 16];
__device__ uint4  g_klo4[MM * HH * 2 / 16];
__device__ uint4  g_vthi4[MM * HH * 2 / 16];  // bf16 [b][h][t]
__device__ uint4  g_vtlo4[MM * HH * 2 / 16];
__device__ uint4  g_wthi4[192 * CC * 2 / 16]; // bf16 Wt [n=192][k=1024]
__device__ uint4  g_wtlo4[192 * CC * 2 / 16];
__device__ float  g_oacc[MM * HH];            // fp32 un-normalized O
__device__ float  g_lacc[MM];                 // fp32 row sums

__device__ __forceinline__ float fast_ex2(float x) {
    float y;
    asm("ex2.approx.ftz.f32 %0, %1;" : "=f"(y) : "f"(x));
    return y;
}
__device__ __forceinline__ uint32_t smem_u32(const void* p) {
    uint32_t a;
    asm("{ .reg .u64 t; cvta.to.shared.u64 t, %1; cvt.u32.u64 %0, t; }"
        : "=r"(a) : "l"(p));
    return a;
}
__device__ __forceinline__ void ldsm4(uint32_t* r, uint32_t addr) {
    asm volatile("ldmatrix.sync.aligned.m8n8.x4.shared.b16 {%0,%1,%2,%3}, [%4];"
                 : "=r"(r[0]), "=r"(r[1]), "=r"(r[2]), "=r"(r[3]) : "r"(addr));
}
__device__ __forceinline__ void mma16816(float* d, const uint32_t* a,
                                         uint32_t b0, uint32_t b1) {
    asm volatile("mma.sync.aligned.m16n8k16.row.col.f32.bf16.bf16.f32 "
                 "{%0,%1,%2,%3}, {%4,%5,%6,%7}, {%8,%9}, {%0,%1,%2,%3};"
                 : "+f"(d[0]), "+f"(d[1]), "+f"(d[2]), "+f"(d[3])
                 : "r"(a[0]), "r"(a[1]), "r"(a[2]), "r"(a[3]), "r"(b0), "r"(b1));
}
__device__ __forceinline__ void cp16(uint32_t dst, const void* src) {
    asm volatile("cp.async.cg.shared.global [%0], [%1], 16;"
                 :: "r"(dst), "l"(src));
}
#define CP_COMMIT() asm volatile("cp.async.commit_group;" ::: "memory")
#define CP_WAIT1()  asm volatile("cp.async.wait_group 1;" ::: "memory")
__device__ __forceinline__ uint32_t packbf2(float lo, float hi) {
    uint32_t r;
    asm("cvt.rn.bf16x2.f32 %0, %1, %2;" : "=r"(r) : "f"(hi), "f"(lo));
    return r;
}
__device__ __forceinline__ float bf16rt(float x) {
    return __bfloat162float(__float2bfloat16_rn(x));
}

// ---------------------------------------------------------------------------
// prep_w: split+transpose W into Wt hi/lo bf16 [n=mat*64+h][k=1024]
// ---------------------------------------------------------------------------
__global__ __launch_bounds__(256) void prep_w(
    const float* __restrict__ Wq, const float* __restrict__ Wk,
    const float* __restrict__ Wv)
{
    __shared__ float ws[64][65];
    const int kc  = blockIdx.x;          // 0..15 (64-k slabs)
    const int mat = blockIdx.y;
    const float* __restrict__ W = (mat == 0) ? Wq : (mat == 1) ? Wk : Wv;
    const int t = threadIdx.x;
    __nv_bfloat16* wth = (__nv_bfloat16*)g_wthi4;
    __nv_bfloat16* wtl = (__nv_bfloat16*)g_wtlo4;

#pragma unroll
    for (int i = 0; i < 16; i++) {
        int idx = t + i * 256;
        int kk = idx >> 6, h = idx & 63;
        ws[kk][h] = W[(size_t)(kc * 64 + kk) * HH + h];
    }
    __syncthreads();
#pragma unroll
    for (int i = 0; i < 16; i++) {
        int idx = t + i * 256;
        int h = idx >> 6, kk = idx & 63;
        float v = ws[kk][h];
        float hb = bf16rt(v);
        size_t o = (size_t)(mat * 64 + h) * CC + kc * 64 + kk;
        wth[o] = __float2bfloat16_rn(hb);
        wtl[o] = __float2bfloat16_rn(v - hb);
    }
}

// ---------------------------------------------------------------------------
// qkv3: fused tensorized projection. [16384 x 1024] @ [1024 x 192].
// 128 CTAs x (128 rows x 192 cols), k-chunk 32, split-bf16 3-pass mma.sync.
// Epilogue: cols 0-63 -> q hi/lo (scaled); 64-127 -> k hi/lo;
//           128-191 -> v, transposed in-CTA to vt [b][h][t] hi/lo.
// smem: A hi/lo [2 buf][128][40bf16] + Wt hi/lo [2 buf][192][40bf16] = 102400 B
// ---------------------------------------------------------------------------
#define QP 80                 // row pitch in bytes (40 bf16)
#define AS_BYTES (128 * QP)   // 10240
#define WS_BYTES (192 * QP)   // 15360
#define OFF_A(buf, sp) ((((buf) * 2 + (sp)) * AS_BYTES))
#define OFF_W(buf, sp) ((4 * AS_BYTES) + (((buf) * 2 + (sp)) * WS_BYTES))
#define QKV3_SMEM (4 * AS_BYTES + 4 * WS_BYTES)   // 102400

__global__ __launch_bounds__(256, 1) void qkv3_kernel(const float* __restrict__ x)
{
    extern __shared__ char smem[];
    const uint32_t sb = smem_u32(smem);
    const int tid  = threadIdx.x;
    const int wid  = tid >> 5;
    const int lane = tid & 31;
    const int wr   = wid >> 1;            // 0..3: rows wr*32
    const int wc   = wid & 1;             // 0..1: cols wc*96
    const int row0 = blockIdx.x * 128;

    const __nv_bfloat16* wth = (const __nv_bfloat16*)g_wthi4;
    const __nv_bfloat16* wtl = (const __nv_bfloat16*)g_wtlo4;

    float acc[2][12][4];
#pragma unroll
    for (int m = 0; m < 2; m++)
#pragma unroll
        for (int j = 0; j < 12; j++)
#pragma unroll
            for (int e = 0; e < 4; e++) acc[m][j][e] = 0.f;

    // A staging: each thread handles rows (tid>>3)+32i, k-quad tid&7
    const int akq = tid & 7, ar = tid >> 3;
    float4 areg[4];
    auto ldgA = [&](int k0) {
#pragma unroll
        for (int it = 0; it < 4; it++)
            areg[it] = *(const float4*)&x[(size_t)(row0 + ar + 32 * it) * CC +
                                          k0 + akq * 4];
    };
    auto stsA = [&](int buf) {
#pragma unroll
        for (int it = 0; it < 4; it++) {
            float4 v = areg[it];
            float hx = bf16rt(v.x), hy = bf16rt(v.y);
            float hz = bf16rt(v.z), hw = bf16rt(v.w);
            uint32_t off = (uint32_t)((ar + 32 * it) * QP + akq * 8);
            *(uint2*)(smem + OFF_A(buf, 0) + off) =
                make_uint2(packbf2(hx, hy), packbf2(hz, hw));
            *(uint2*)(smem + OFF_A(buf, 1) + off) =
                make_uint2(packbf2(v.x - hx, v.y - hy),
                           packbf2(v.z - hz, v.w - hw));
        }
    };
    auto cpW = [&](int buf, int k0) {
#pragma unroll
        for (int i = 0; i < 3; i++) {
            int idx = tid + i * 256;      // 0..767
            int n = idx >> 2, seg = idx & 3;
            uint32_t d = (uint32_t)(n * QP + seg * 16);
            cp16(sb + OFF_W(buf, 0) + d, wth + (size_t)n * CC + k0 + seg * 8);
            cp16(sb + OFF_W(buf, 1) + d, wtl + (size_t)n * CC + k0 + seg * 8);
        }
    };

    // ldmatrix lane addressing
    const uint32_t a_off = (uint32_t)((wr * 32 + (lane & 15)) * QP +
                                      (lane >> 4) * 16);
    const int b_row  = (lane & 7) + ((lane >> 4) & 1) * 8;
    const int b_sel  = (lane >> 3) & 1;
    const uint32_t b_off = (uint32_t)((wc * 96 + b_row) * QP + b_sel * 16);

    // prologue
    ldgA(0); stsA(0);
    cpW(0, 0); CP_COMMIT();
    ldgA(32);

    for (int kc = 0; kc < 32; kc++) {
        const int buf = kc & 1;
        if (kc + 1 < 32) cpW(buf ^ 1, (kc + 1) * 32);
        CP_COMMIT();
        CP_WAIT1();
        __syncthreads();

        const uint32_t ah_b = sb + OFF_A(buf, 0) + a_off;
        const uint32_t al_b = sb + OFF_A(buf, 1) + a_off;
        const uint32_t bh_b = sb + OFF_W(buf, 0) + b_off;
        const uint32_t bl_b = sb + OFF_W(buf, 1) + b_off;
#pragma unroll
        for (int ks = 0; ks < 2; ks++) {
            uint32_t ah[2][4], al[2][4];
            ldsm4(ah[0], ah_b + ks * 32);
            ldsm4(ah[1], ah_b + 16 * QP + ks * 32);
            ldsm4(al[0], al_b + ks * 32);
            ldsm4(al[1], al_b + 16 * QP + ks * 32);
#pragma unroll
            for (int j = 0; j < 6; j++) {
                uint32_t bh[4], bl[4];
                ldsm4(bh, bh_b + j * 16 * QP + ks * 32);
                ldsm4(bl, bl_b + j * 16 * QP + ks * 32);
#pragma unroll
                for (int m = 0; m < 2; m++) {
                    mma16816(acc[m][2 * j],     ah[m], bh[0], bh[1]);
                    mma16816(acc[m][2 * j],     al[m], bh[0], bh[1]);
                    mma16816(acc[m][2 * j],     ah[m], bl[0], bl[1]);
                    mma16816(acc[m][2 * j + 1], ah[m], bh[2], bh[3]);
                    mma16816(acc[m][2 * j + 1], al[m], bh[2], bh[3]);
                    mma16816(acc[m][2 * j + 1], ah[m], bl[2], bl[3]);
                }
            }
        }

        if (kc + 1 < 32) {
            __syncthreads();              // MMA reads of buf^1 done (prev iter)
            stsA(buf ^ 1);
            if (kc + 2 < 32) ldgA((kc + 2) * 32);
        }
    }
    __syncthreads();

    // ---- epilogue ----
    __nv_bfloat16* qh = (__nv_bfloat16*)g_qhi4;
    __nv_bfloat16* ql = (__nv_bfloat16*)g_qlo4;
    __nv_bfloat16* kh = (__nv_bfloat16*)g_khi4;
    __nv_bfloat16* kl = (__nv_bfloat16*)g_klo4;
    float* vbuf = (float*)smem;           // [128][65] fp32 (reuses gemm smem)
    const int fr = lane >> 2, fc = (lane & 3) * 2;

#pragma unroll
    for (int m = 0; m < 2; m++)
#pragma unroll
        for (int j = 0; j < 12; j++) {
            const int c = wc * 96 + j * 8 + fc;
            const int r = row0 + wr * 32 + m * 16 + fr;
            const float* a = acc[m][j];
            if (c < 128) {
                const bool isq = (c < 64);
                const float sc = isq ? SM_SCALE_LOG2E : 1.0f;
                __nv_bfloat16* oh = isq ? qh : kh;
                __nv_bfloat16* ol = isq ? ql : kl;
                const int cc = c & 63;
#pragma unroll
                for (int rr = 0; rr < 2; rr++) {
                    float v0 = a[2 * rr] * sc, v1 = a[2 * rr + 1] * sc;
                    float h0 = bf16rt(v0), h1 = bf16rt(v1);
                    size_t o = (size_t)(r + rr * 8) * HH + cc;
                    *(uint32_t*)&oh[o] = packbf2(h0, h1);
                    *(uint32_t*)&ol[o] = packbf2(v0 - h0, v1 - h1);
                }
            } else {
                const int ch = c - 128;
                const int rl = r - row0;
                vbuf[rl * 65 + ch]       = a[0];
                vbuf[rl * 65 + ch + 1]   = a[1];
                vbuf[(rl + 8) * 65 + ch]     = a[2];
                vbuf[(rl + 8) * 65 + ch + 1] = a[3];
            }
        }
    __syncthreads();

    // transposed vt store: [b][h][t] hi/lo
    {
        __nv_bfloat16* vth = (__nv_bfloat16*)g_vthi4;
        __nv_bfloat16* vtl = (__nv_bfloat16*)g_vtlo4;
        const int bidx = row0 >> 12;      // /4096
        const int t0   = row0 & 4095;
#pragma unroll
        for (int i = 0; i < 32; i++) {
            int idx = tid + i * 256;      // 0..8191
            int h = idx >> 7, tt = idx & 127;
            float v = vbuf[tt * 65 + h];
            float hb = bf16rt(v);
            size_t o = (size_t)(bidx * HH + h) * TT + t0 + tt;
            vth[o] = __float2bfloat16_rn(hb);
            vtl[o] = __float2bfloat16_rn(v - hb);
        }
    }
}

// ---------------------------------------------------------------------------
// zero accumulators
// ---------------------------------------------------------------------------
__global__ __launch_bounds__(256) void zero_acc()
{
    int i = blockIdx.x * 256 + threadIdx.x;
    ((float4*)g_oacc)[i] = make_float4(0.f, 0.f, 0.f, 0.f);
    if (i < MM / 4)
        ((float4*)g_lacc)[i] = make_float4(0.f, 0.f, 0.f, 0.f);
}

// ---------------------------------------------------------------------------
// mma.sync flash attention (split-bf16, no-rescale softmax, split-K units).
// Q fragments hoisted into registers (reloaded only on q-tile change).
// ---------------------------------------------------------------------------
#define UPITCH 144            // 72 bf16 per row
#define OFF_QHI 0
#define OFF_QLO 18432
#define OFF_ST  36864
#define ST_STRIDE 36864
#define ST_KHI 0
#define ST_KLO 9216
#define ST_VHI 18432
#define ST_VLO 27648
#define ATT_SMEM 110592
#define NCTA 148
#define UNITS_PER_B 1056
#define TOTAL_UNITS (BB * UNITS_PER_B)

__device__ __forceinline__ void decode_unit(int u, int& b, int& qt, int& kc) {
    b = u / UNITS_PER_B;
    int r = u - b * UNITS_PER_B;
    int q = (int)((sqrtf(4.f * (float)r + 1.f) - 1.f) * 0.5f);
    while ((q + 1) * (q + 2) <= r) q++;
    while (q * (q + 1) > r) q--;
    qt = q;
    kc = r - q * (q + 1);
}

__global__ __launch_bounds__(256, 1) void attn_kernel()
{
    extern __shared__ char smem[];
    const uint32_t sb = smem_u32(smem);

    const int tid  = threadIdx.x;
    const int wid  = tid >> 5;
    const int lane = tid & 31;

    const __nv_bfloat16* gqh = (const __nv_bfloat16*)g_qhi4;
    const __nv_bfloat16* gql = (const __nv_bfloat16*)g_qlo4;
    const __nv_bfloat16* gkh = (const __nv_bfloat16*)g_khi4;
    const __nv_bfloat16* gkl = (const __nv_bfloat16*)g_klo4;
    const __nv_bfloat16* gvh = (const __nv_bfloat16*)g_vthi4;
    const __nv_bfloat16* gvl = (const __nv_bfloat16*)g_vtlo4;

    const int u0 = (int)(((long long)TOTAL_UNITS * blockIdx.x) / NCTA);
    const int u1 = (int)(((long long)TOTAL_UNITS * (blockIdx.x + 1)) / NCTA);

    const int a_row  = wid * 16 + (lane & 15);
    const int a_csel = (lane >> 4) & 1;
    const uint32_t qh_base = sb + OFF_QHI + a_row * UPITCH + a_csel * 16;
    const uint32_t ql_base = sb + OFF_QLO + a_row * UPITCH + a_csel * 16;
    const int b_key  = (lane & 7) + ((lane >> 4) & 1) * 8;
    const int b_hsel = (lane >> 3) & 1;
    const int v_h    = (lane & 7) + ((lane >> 4) & 1) * 8;
    const int v_ksel = (lane >> 3) & 1;

    auto prefetch = [&](int st, int b, int kc) {
        uint32_t so = sb + OFF_ST + st * ST_STRIDE;
        const __nv_bfloat16* kh = gkh + (size_t)(b * TT + kc * 64) * HH;
        const __nv_bfloat16* kl = gkl + (size_t)(b * TT + kc * 64) * HH;
        const __nv_bfloat16* vh = gvh + (size_t)b * HH * TT + (size_t)kc * 64;
        const __nv_bfloat16* vl = gvl + (size_t)b * HH * TT + (size_t)kc * 64;
#pragma unroll
        for (int i = 0; i < 2; i++) {
            int idx = tid + i * 256;
            int r = idx >> 3, c = idx & 7;
            uint32_t d = r * UPITCH + c * 16;
            cp16(so + ST_KHI + d, kh + (size_t)r * HH + c * 8);
            cp16(so + ST_KLO + d, kl + (size_t)r * HH + c * 8);
            cp16(so + ST_VHI + d, vh + (size_t)r * TT + c * 8);
            cp16(so + ST_VLO + d, vl + (size_t)r * TT + c * 8);
        }
    };

    {
        int b, qt, kc;
        decode_unit(u0, b, qt, kc);
        prefetch(u0 & 1, b, kc);
        CP_COMMIT();
        if (u0 + 1 < u1) {
            decode_unit(u0 + 1, b, qt, kc);
            prefetch((u0 + 1) & 1, b, kc);
        }
        CP_COMMIT();
    }

    float of[8][4];
    float lsum0 = 0.f, lsum1 = 0.f;
    int cur_b = -1, cur_qt = -1;
    uint32_t qah[4][4], qal[4][4];        // hoisted Q fragments

    auto flush = [&](int cb, int cq) {
        float s0 = lsum0, s1 = lsum1;
#pragma unroll
        for (int d = 1; d < 4; d <<= 1) {
            s0 += __shfl_xor_sync(0xffffffffu, s0, d);
            s1 += __shfl_xor_sync(0xffffffffu, s1, d);
        }
        int qb = cb * TT + cq * 128;
        int row0 = qb + wid * 16 + (lane >> 2);
        if ((lane & 3) == 0) {
            atomicAdd(&g_lacc[row0], s0);
            atomicAdd(&g_lacc[row0 + 8], s1);
        }
#pragma unroll
        for (int n8 = 0; n8 < 8; n8++) {
            int col = n8 * 8 + (lane & 3) * 2;
            atomicAdd(&g_oacc[(size_t)row0 * HH + col],           of[n8][0]);
            atomicAdd(&g_oacc[(size_t)row0 * HH + col + 1],       of[n8][1]);
            atomicAdd(&g_oacc[(size_t)(row0 + 8) * HH + col],     of[n8][2]);
            atomicAdd(&g_oacc[(size_t)(row0 + 8) * HH + col + 1], of[n8][3]);
        }
    };

    for (int u = u0; u < u1; u++) {
        int b, qt, kc;
        decode_unit(u, b, qt, kc);

        CP_WAIT1();
        __syncthreads();

        if (b != cur_b || qt != cur_qt) {
            if (cur_qt >= 0) flush(cur_b, cur_qt);
#pragma unroll
            for (int i = 0; i < 8; i++)
#pragma unroll
                for (int j = 0; j < 4; j++) of[i][j] = 0.f;
            lsum0 = lsum1 = 0.f;
            const __nv_bfloat16* qhp = gqh + (size_t)(b * TT + qt * 128) * HH;
            const __nv_bfloat16* qlp = gql + (size_t)(b * TT + qt * 128) * HH;
#pragma unroll
            for (int i = 0; i < 4; i++) {
                int idx = tid + i * 256;
                int r = idx >> 3, c = idx & 7;
                *(uint4*)(smem + OFF_QHI + r * UPITCH + c * 16) =
                    *(const uint4*)(qhp + (size_t)r * HH + c * 8);
                *(uint4*)(smem + OFF_QLO + r * UPITCH + c * 16) =
                    *(const uint4*)(qlp + (size_t)r * HH + c * 8);
            }
            __syncthreads();
#pragma unroll
            for (int ks = 0; ks < 4; ks++) {
                ldsm4(qah[ks], qh_base + ks * 32);
                ldsm4(qal[ks], ql_base + ks * 32);
            }
            cur_b = b; cur_qt = qt;
        }

        const uint32_t so = sb + OFF_ST + (u & 1) * ST_STRIDE;

        // ---- S = Q K^T ----
        float sf[8][4];
#pragma unroll
        for (int i = 0; i < 8; i++)
#pragma unroll
            for (int j = 0; j < 4; j++) sf[i][j] = 0.f;

#pragma unroll
        for (int ks = 0; ks < 4; ks++) {
#pragma unroll
            for (int g = 0; g < 4; g++) {
                uint32_t bh[4], bl[4];
                uint32_t ka = so + (16 * g + b_key) * UPITCH + ks * 32 + b_hsel * 16;
                ldsm4(bh, ka + ST_KHI);
                ldsm4(bl, ka + ST_KLO);
                mma16816(sf[2 * g],     qah[ks], bh[0], bh[1]);
                mma16816(sf[2 * g],     qal[ks], bh[0], bh[1]);
                mma16816(sf[2 * g],     qah[ks], bl[0], bl[1]);
                mma16816(sf[2 * g + 1], qah[ks], bh[2], bh[3]);
                mma16816(sf[2 * g + 1], qal[ks], bh[2], bh[3]);
                mma16816(sf[2 * g + 1], qah[ks], bl[2], bl[3]);
            }
        }

        // ---- softmax + P hi/lo fragments ----
        const bool needmask = (kc >= 2 * qt);
        const int qrow0 = qt * 128 + wid * 16 + (lane >> 2);
        const int keyb  = kc * 64 + (lane & 3) * 2;
        uint32_t phi[8][2], plo[8][2];
#pragma unroll
        for (int n8 = 0; n8 < 8; n8++) {
            int k0 = keyb + n8 * 8;
            float p0 = fast_ex2(sf[n8][0]);
            float p1 = fast_ex2(sf[n8][1]);
            float p2 = fast_ex2(sf[n8][2]);
            float p3 = fast_ex2(sf[n8][3]);
            if (needmask) {
                if (k0     > qrow0)     p0 = 0.f;
                if (k0 + 1 > qrow0)     p1 = 0.f;
                if (k0     > qrow0 + 8) p2 = 0.f;
                if (k0 + 1 > qrow0 + 8) p3 = 0.f;
            }
            lsum0 += p0 + p1;
            lsum1 += p2 + p3;
            float h0 = bf16rt(p0), h1 = bf16rt(p1), h2 = bf16rt(p2), h3 = bf16rt(p3);
            phi[n8][0] = packbf2(h0, h1);
            phi[n8][1] = packbf2(h2, h3);
            plo[n8][0] = packbf2(p0 - h0, p1 - h1);
            plo[n8][1] = packbf2(p2 - h2, p3 - h3);
        }

        // ---- O += P V ----
#pragma unroll
        for (int ks = 0; ks < 4; ks++) {
            uint32_t pah[4] = { phi[2 * ks][0], phi[2 * ks][1],
                                phi[2 * ks + 1][0], phi[2 * ks + 1][1] };
            uint32_t pal[4] = { plo[2 * ks][0], plo[2 * ks][1],
                                plo[2 * ks + 1][0], plo[2 * ks + 1][1] };
#pragma unroll
            for (int g = 0; g < 4; g++) {
                uint32_t vh[4], vl[4];
                uint32_t va = so + (16 * g + v_h) * UPITCH + ks * 32 + v_ksel * 16;
                ldsm4(vh, va + ST_VHI);
                ldsm4(vl, va + ST_VLO);
                mma16816(of[2 * g],     pah, vh[0], vh[1]);
                mma16816(of[2 * g],     pal, vh[0], vh[1]);
                mma16816(of[2 * g],     pah, vl[0], vl[1]);
                mma16816(of[2 * g + 1], pah, vh[2], vh[3]);
                mma16816(of[2 * g + 1], pal, vh[2], vh[3]);
                mma16816(of[2 * g + 1], pah, vl[2], vl[3]);
            }
        }

        __syncthreads();
        if (u + 2 < u1) {
            int nb, nqt, nkc;
            decode_unit(u + 2, nb, nqt, nkc);
            prefetch(u & 1, nb, nkc);
        }
        CP_COMMIT();
    }

    flush(cur_b, cur_qt);
}

// ---------------------------------------------------------------------------
// finalize: out = O_acc / l
// ---------------------------------------------------------------------------
__global__ __launch_bounds__(256) void finalize(float* __restrict__ out)
{
    int i = blockIdx.x * 256 + threadIdx.x;
    float4 o = ((const float4*)g_oacc)[i];
    float inv = 1.0f / g_lacc[i >> 4];
    o.x *= inv; o.y *= inv; o.z *= inv; o.w *= inv;
    ((float4*)out)[i] = o;
}

// ---------------------------------------------------------------------------
extern "C" void kernel_launch(void* const* d_in, const int* in_sizes, int n_in,
                              void* d_out, int out_size)
{
    const float* x  = (const float*)d_in[0];
    const float* Wq = (const float*)d_in[1];
    const float* Wk = (const float*)d_in[2];
    const float* Wv = (const float*)d_in[3];
    float* out = (float*)d_out;

    cudaFuncSetAttribute(qkv3_kernel,
                         cudaFuncAttributeMaxDynamicSharedMemorySize, QKV3_SMEM);
    cudaFuncSetAttribute(attn_kernel,
                         cudaFuncAttributeMaxDynamicSharedMemorySize, ATT_SMEM);

    dim3 pw_grid(16, 3);
    prep_w<<<pw_grid, 256>>>(Wq, Wk, Wv);

    qkv3_kernel<<<MM / 128, 256, QKV3_SMEM>>>(x);

    zero_acc<<<MM * HH / 4 / 256, 256>>>();

    attn_kernel<<<NCTA, 256, ATT_SMEM>>>();

    finalize<<<MM * HH / 4 / 256, 256>>>(out);
}

// round 6
// speedup vs baseline: 4.0983x; 1.0607x over previous
#include <cuda_runtime.h>
#include <cuda_bf16.h>
#include <cstdint>

// Problem constants
#define BB 4
#define TT 4096
#define CC 1024
#define HH 64
#define MM (BB * TT)          // 16384 rows

#define SM_SCALE_LOG2E (0.03125f * 1.4426950408889634f)

// ---------------------------------------------------------------------------
// Global scratch
// ---------------------------------------------------------------------------
__device__ uint4  g_qhi4[MM * HH * 2 / 16];   // bf16 [m][64]
__device__ uint4  g_qlo4[MM * HH * 2 / 16];
__device__ uint4  g_khi4[MM * HH * 2 / 16];
__device__ uint4  g_klo4[MM * HH * 2 / 16];
__device__ uint4  g_vthi4[MM * HH * 2 / 16];  // bf16 [b][h][t]
__device__ uint4  g_vtlo4[MM * HH * 2 / 16];
__device__ uint4  g_wthi4[192 * CC * 2 / 16]; // bf16 Wt [n=192][k=1024]
__device__ uint4  g_wtlo4[192 * CC * 2 / 16];
__device__ float  g_oacc[MM * HH];            // fp32 un-normalized O
__device__ float  g_lacc[MM];                 // fp32 row sums

__device__ __forceinline__ float fast_ex2(float x) {
    float y;
    asm("ex2.approx.ftz.f32 %0, %1;" : "=f"(y) : "f"(x));
    return y;
}
__device__ __forceinline__ uint32_t smem_u32(const void* p) {
    uint32_t a;
    asm("{ .reg .u64 t; cvta.to.shared.u64 t, %1; cvt.u32.u64 %0, t; }"
        : "=r"(a) : "l"(p));
    return a;
}
__device__ __forceinline__ void ldsm4(uint32_t* r, uint32_t addr) {
    asm volatile("ldmatrix.sync.aligned.m8n8.x4.shared.b16 {%0,%1,%2,%3}, [%4];"
                 : "=r"(r[0]), "=r"(r[1]), "=r"(r[2]), "=r"(r[3]) : "r"(addr));
}
__device__ __forceinline__ void mma16816(float* d, const uint32_t* a,
                                         uint32_t b0, uint32_t b1) {
    asm volatile("mma.sync.aligned.m16n8k16.row.col.f32.bf16.bf16.f32 "
                 "{%0,%1,%2,%3}, {%4,%5,%6,%7}, {%8,%9}, {%0,%1,%2,%3};"
                 : "+f"(d[0]), "+f"(d[1]), "+f"(d[2]), "+f"(d[3])
                 : "r"(a[0]), "r"(a[1]), "r"(a[2]), "r"(a[3]), "r"(b0), "r"(b1));
}
__device__ __forceinline__ void cp16(uint32_t dst, const void* src) {
    asm volatile("cp.async.cg.shared.global [%0], [%1], 16;"
                 :: "r"(dst), "l"(src));
}
#define CP_COMMIT() asm volatile("cp.async.commit_group;" ::: "memory")
#define CP_WAIT1()  asm volatile("cp.async.wait_group 1;" ::: "memory")
__device__ __forceinline__ uint32_t packbf2(float lo, float hi) {
    uint32_t r;
    asm("cvt.rn.bf16x2.f32 %0, %1, %2;" : "=r"(r) : "f"(hi), "f"(lo));
    return r;
}
__device__ __forceinline__ float bf16rt(float x) {
    return __bfloat162float(__float2bfloat16_rn(x));
}

// ---------------------------------------------------------------------------
// prep_w: split+transpose W into Wt hi/lo bf16 [n=mat*64+h][k=1024]
// ---------------------------------------------------------------------------
__global__ __launch_bounds__(256) void prep_w(
    const float* __restrict__ Wq, const float* __restrict__ Wk,
    const float* __restrict__ Wv)
{
    __shared__ float ws[64][65];
    const int kc  = blockIdx.x;          // 0..15 (64-k slabs)
    const int mat = blockIdx.y;
    const float* __restrict__ W = (mat == 0) ? Wq : (mat == 1) ? Wk : Wv;
    const int t = threadIdx.x;
    __nv_bfloat16* wth = (__nv_bfloat16*)g_wthi4;
    __nv_bfloat16* wtl = (__nv_bfloat16*)g_wtlo4;

#pragma unroll
    for (int i = 0; i < 16; i++) {
        int idx = t + i * 256;
        int kk = idx >> 6, h = idx & 63;
        ws[kk][h] = W[(size_t)(kc * 64 + kk) * HH + h];
    }
    __syncthreads();
#pragma unroll
    for (int i = 0; i < 16; i++) {
        int idx = t + i * 256;
        int h = idx >> 6, kk = idx & 63;
        float v = ws[kk][h];
        float hb = bf16rt(v);
        size_t o = (size_t)(mat * 64 + h) * CC + kc * 64 + kk;
        wth[o] = __float2bfloat16_rn(hb);
        wtl[o] = __float2bfloat16_rn(v - hb);
    }
}

// ---------------------------------------------------------------------------
// qkv3: fused tensorized projection. [16384 x 1024] @ [1024 x 192].
// ---------------------------------------------------------------------------
#define QP 80                 // row pitch in bytes (40 bf16)
#define AS_BYTES (128 * QP)   // 10240
#define WS_BYTES (192 * QP)   // 15360
#define OFF_A(buf, sp) ((((buf) * 2 + (sp)) * AS_BYTES))
#define OFF_W(buf, sp) ((4 * AS_BYTES) + (((buf) * 2 + (sp)) * WS_BYTES))
#define QKV3_SMEM (4 * AS_BYTES + 4 * WS_BYTES)   // 102400

__global__ __launch_bounds__(256, 1) void qkv3_kernel(const float* __restrict__ x)
{
    extern __shared__ char smem[];
    const uint32_t sb = smem_u32(smem);
    const int tid  = threadIdx.x;
    const int wid  = tid >> 5;
    const int lane = tid & 31;
    const int wr   = wid >> 1;            // 0..3: rows wr*32
    const int wc   = wid & 1;             // 0..1: cols wc*96
    const int row0 = blockIdx.x * 128;

    const __nv_bfloat16* wth = (const __nv_bfloat16*)g_wthi4;
    const __nv_bfloat16* wtl = (const __nv_bfloat16*)g_wtlo4;

    float acc[2][12][4];
#pragma unroll
    for (int m = 0; m < 2; m++)
#pragma unroll
        for (int j = 0; j < 12; j++)
#pragma unroll
            for (int e = 0; e < 4; e++) acc[m][j][e] = 0.f;

    const int akq = tid & 7, ar = tid >> 3;
    float4 areg[4];
    auto ldgA = [&](int k0) {
#pragma unroll
        for (int it = 0; it < 4; it++)
            areg[it] = *(const float4*)&x[(size_t)(row0 + ar + 32 * it) * CC +
                                          k0 + akq * 4];
    };
    auto stsA = [&](int buf) {
#pragma unroll
        for (int it = 0; it < 4; it++) {
            float4 v = areg[it];
            float hx = bf16rt(v.x), hy = bf16rt(v.y);
            float hz = bf16rt(v.z), hw = bf16rt(v.w);
            uint32_t off = (uint32_t)((ar + 32 * it) * QP + akq * 8);
            *(uint2*)(smem + OFF_A(buf, 0) + off) =
                make_uint2(packbf2(hx, hy), packbf2(hz, hw));
            *(uint2*)(smem + OFF_A(buf, 1) + off) =
                make_uint2(packbf2(v.x - hx, v.y - hy),
                           packbf2(v.z - hz, v.w - hw));
        }
    };
    auto cpW = [&](int buf, int k0) {
#pragma unroll
        for (int i = 0; i < 3; i++) {
            int idx = tid + i * 256;      // 0..767
            int n = idx >> 2, seg = idx & 3;
            uint32_t d = (uint32_t)(n * QP + seg * 16);
            cp16(sb + OFF_W(buf, 0) + d, wth + (size_t)n * CC + k0 + seg * 8);
            cp16(sb + OFF_W(buf, 1) + d, wtl + (size_t)n * CC + k0 + seg * 8);
        }
    };

    const uint32_t a_off = (uint32_t)((wr * 32 + (lane & 15)) * QP +
                                      (lane >> 4) * 16);
    const int b_row  = (lane & 7) + ((lane >> 4) & 1) * 8;
    const int b_sel  = (lane >> 3) & 1;
    const uint32_t b_off = (uint32_t)((wc * 96 + b_row) * QP + b_sel * 16);

    ldgA(0); stsA(0);
    cpW(0, 0); CP_COMMIT();
    ldgA(32);

    for (int kc = 0; kc < 32; kc++) {
        const int buf = kc & 1;
        if (kc + 1 < 32) cpW(buf ^ 1, (kc + 1) * 32);
        CP_COMMIT();
        CP_WAIT1();
        __syncthreads();

        const uint32_t ah_b = sb + OFF_A(buf, 0) + a_off;
        const uint32_t al_b = sb + OFF_A(buf, 1) + a_off;
        const uint32_t bh_b = sb + OFF_W(buf, 0) + b_off;
        const uint32_t bl_b = sb + OFF_W(buf, 1) + b_off;
#pragma unroll
        for (int ks = 0; ks < 2; ks++) {
            uint32_t ah[2][4], al[2][4];
            ldsm4(ah[0], ah_b + ks * 32);
            ldsm4(ah[1], ah_b + 16 * QP + ks * 32);
            ldsm4(al[0], al_b + ks * 32);
            ldsm4(al[1], al_b + 16 * QP + ks * 32);
#pragma unroll
            for (int j = 0; j < 6; j++) {
                uint32_t bh[4], bl[4];
                ldsm4(bh, bh_b + j * 16 * QP + ks * 32);
                ldsm4(bl, bl_b + j * 16 * QP + ks * 32);
#pragma unroll
                for (int m = 0; m < 2; m++) {
                    mma16816(acc[m][2 * j],     ah[m], bh[0], bh[1]);
                    mma16816(acc[m][2 * j],     al[m], bh[0], bh[1]);
                    mma16816(acc[m][2 * j],     ah[m], bl[0], bl[1]);
                    mma16816(acc[m][2 * j + 1], ah[m], bh[2], bh[3]);
                    mma16816(acc[m][2 * j + 1], al[m], bh[2], bh[3]);
                    mma16816(acc[m][2 * j + 1], ah[m], bl[2], bl[3]);
                }
            }
        }

        if (kc + 1 < 32) {
            __syncthreads();
            stsA(buf ^ 1);
            if (kc + 2 < 32) ldgA((kc + 2) * 32);
        }
    }
    __syncthreads();

    // ---- epilogue ----
    __nv_bfloat16* qh = (__nv_bfloat16*)g_qhi4;
    __nv_bfloat16* ql = (__nv_bfloat16*)g_qlo4;
    __nv_bfloat16* kh = (__nv_bfloat16*)g_khi4;
    __nv_bfloat16* kl = (__nv_bfloat16*)g_klo4;
    float* vbuf = (float*)smem;           // [128][65] fp32
    const int fr = lane >> 2, fc = (lane & 3) * 2;

#pragma unroll
    for (int m = 0; m < 2; m++)
#pragma unroll
        for (int j = 0; j < 12; j++) {
            const int c = wc * 96 + j * 8 + fc;
            const int r = row0 + wr * 32 + m * 16 + fr;
            const float* a = acc[m][j];
            if (c < 128) {
                const bool isq = (c < 64);
                const float sc = isq ? SM_SCALE_LOG2E : 1.0f;
                __nv_bfloat16* oh = isq ? qh : kh;
                __nv_bfloat16* ol = isq ? ql : kl;
                const int cc = c & 63;
#pragma unroll
                for (int rr = 0; rr < 2; rr++) {
                    float v0 = a[2 * rr] * sc, v1 = a[2 * rr + 1] * sc;
                    float h0 = bf16rt(v0), h1 = bf16rt(v1);
                    size_t o = (size_t)(r + rr * 8) * HH + cc;
                    *(uint32_t*)&oh[o] = packbf2(h0, h1);
                    *(uint32_t*)&ol[o] = packbf2(v0 - h0, v1 - h1);
                }
            } else {
                const int ch = c - 128;
                const int rl = r - row0;
                vbuf[rl * 65 + ch]       = a[0];
                vbuf[rl * 65 + ch + 1]   = a[1];
                vbuf[(rl + 8) * 65 + ch]     = a[2];
                vbuf[(rl + 8) * 65 + ch + 1] = a[3];
            }
        }
    __syncthreads();

    {
        __nv_bfloat16* vth = (__nv_bfloat16*)g_vthi4;
        __nv_bfloat16* vtl = (__nv_bfloat16*)g_vtlo4;
        const int bidx = row0 >> 12;
        const int t0   = row0 & 4095;
#pragma unroll
        for (int i = 0; i < 32; i++) {
            int idx = tid + i * 256;
            int h = idx >> 7, tt = idx & 127;
            float v = vbuf[tt * 65 + h];
            float hb = bf16rt(v);
            size_t o = (size_t)(bidx * HH + h) * TT + t0 + tt;
            vth[o] = __float2bfloat16_rn(hb);
            vtl[o] = __float2bfloat16_rn(v - hb);
        }
    }
}

// ---------------------------------------------------------------------------
// zero accumulators
// ---------------------------------------------------------------------------
__global__ __launch_bounds__(256) void zero_acc()
{
    int i = blockIdx.x * 256 + threadIdx.x;
    ((float4*)g_oacc)[i] = make_float4(0.f, 0.f, 0.f, 0.f);
    if (i < MM / 4)
        ((float4*)g_lacc)[i] = make_float4(0.f, 0.f, 0.f, 0.f);
}

// ---------------------------------------------------------------------------
// mma.sync flash attention. Register-dieted for 2 CTAs/SM:
//  - Q fragments re-loaded per unit (ldsm) instead of hoisted
//  - softmax+PV fused per 16-col P chunk (phi/plo live regs: 8)
// 296 persistent CTAs (2/SM); units balanced contiguously.
// ---------------------------------------------------------------------------
#define UPITCH 144            // 72 bf16 per row
#define OFF_QHI 0
#define OFF_QLO 18432
#define OFF_ST  36864
#define ST_STRIDE 36864
#define ST_KHI 0
#define ST_KLO 9216
#define ST_VHI 18432
#define ST_VLO 27648
#define ATT_SMEM 110592
#define ATT_NCTA 296
#define UNITS_PER_B 1056
#define TOTAL_UNITS (BB * UNITS_PER_B)

__device__ __forceinline__ void decode_unit(int u, int& b, int& qt, int& kc) {
    b = u / UNITS_PER_B;
    int r = u - b * UNITS_PER_B;
    int q = (int)((sqrtf(4.f * (float)r + 1.f) - 1.f) * 0.5f);
    while ((q + 1) * (q + 2) <= r) q++;
    while (q * (q + 1) > r) q--;
    qt = q;
    kc = r - q * (q + 1);
}

__global__ __launch_bounds__(256, 2) void attn_kernel()
{
    extern __shared__ char smem[];
    const uint32_t sb = smem_u32(smem);

    const int tid  = threadIdx.x;
    const int wid  = tid >> 5;
    const int lane = tid & 31;

    const __nv_bfloat16* gqh = (const __nv_bfloat16*)g_qhi4;
    const __nv_bfloat16* gql = (const __nv_bfloat16*)g_qlo4;
    const __nv_bfloat16* gkh = (const __nv_bfloat16*)g_khi4;
    const __nv_bfloat16* gkl = (const __nv_bfloat16*)g_klo4;
    const __nv_bfloat16* gvh = (const __nv_bfloat16*)g_vthi4;
    const __nv_bfloat16* gvl = (const __nv_bfloat16*)g_vtlo4;

    const int u0 = (int)(((long long)TOTAL_UNITS * blockIdx.x) / ATT_NCTA);
    const int u1 = (int)(((long long)TOTAL_UNITS * (blockIdx.x + 1)) / ATT_NCTA);

    const int a_row  = wid * 16 + (lane & 15);
    const int a_csel = (lane >> 4) & 1;
    const uint32_t qh_base = sb + OFF_QHI + a_row * UPITCH + a_csel * 16;
    const uint32_t ql_base = sb + OFF_QLO + a_row * UPITCH + a_csel * 16;
    const int b_key  = (lane & 7) + ((lane >> 4) & 1) * 8;
    const int b_hsel = (lane >> 3) & 1;
    const int v_h    = (lane & 7) + ((lane >> 4) & 1) * 8;
    const int v_ksel = (lane >> 3) & 1;

    auto prefetch = [&](int st, int b, int kc) {
        uint32_t so = sb + OFF_ST + st * ST_STRIDE;
        const __nv_bfloat16* kh = gkh + (size_t)(b * TT + kc * 64) * HH;
        const __nv_bfloat16* kl = gkl + (size_t)(b * TT + kc * 64) * HH;
        const __nv_bfloat16* vh = gvh + (size_t)b * HH * TT + (size_t)kc * 64;
        const __nv_bfloat16* vl = gvl + (size_t)b * HH * TT + (size_t)kc * 64;
#pragma unroll
        for (int i = 0; i < 2; i++) {
            int idx = tid + i * 256;
            int r = idx >> 3, c = idx & 7;
            uint32_t d = r * UPITCH + c * 16;
            cp16(so + ST_KHI + d, kh + (size_t)r * HH + c * 8);
            cp16(so + ST_KLO + d, kl + (size_t)r * HH + c * 8);
            cp16(so + ST_VHI + d, vh + (size_t)r * TT + c * 8);
            cp16(so + ST_VLO + d, vl + (size_t)r * TT + c * 8);
        }
    };

    {
        int b, qt, kc;
        decode_unit(u0, b, qt, kc);
        prefetch(u0 & 1, b, kc);
        CP_COMMIT();
        if (u0 + 1 < u1) {
            decode_unit(u0 + 1, b, qt, kc);
            prefetch((u0 + 1) & 1, b, kc);
        }
        CP_COMMIT();
    }

    float of[8][4];
    float lsum0 = 0.f, lsum1 = 0.f;
    int cur_b = -1, cur_qt = -1;

    auto flush = [&](int cb, int cq) {
        float s0 = lsum0, s1 = lsum1;
#pragma unroll
        for (int d = 1; d < 4; d <<= 1) {
            s0 += __shfl_xor_sync(0xffffffffu, s0, d);
            s1 += __shfl_xor_sync(0xffffffffu, s1, d);
        }
        int qb = cb * TT + cq * 128;
        int row0 = qb + wid * 16 + (lane >> 2);
        if ((lane & 3) == 0) {
            atomicAdd(&g_lacc[row0], s0);
            atomicAdd(&g_lacc[row0 + 8], s1);
        }
#pragma unroll
        for (int n8 = 0; n8 < 8; n8++) {
            int col = n8 * 8 + (lane & 3) * 2;
            atomicAdd(&g_oacc[(size_t)row0 * HH + col],           of[n8][0]);
            atomicAdd(&g_oacc[(size_t)row0 * HH + col + 1],       of[n8][1]);
            atomicAdd(&g_oacc[(size_t)(row0 + 8) * HH + col],     of[n8][2]);
            atomicAdd(&g_oacc[(size_t)(row0 + 8) * HH + col + 1], of[n8][3]);
        }
    };

    for (int u = u0; u < u1; u++) {
        int b, qt, kc;
        decode_unit(u, b, qt, kc);

        CP_WAIT1();
        __syncthreads();

        if (b != cur_b || qt != cur_qt) {
            if (cur_qt >= 0) flush(cur_b, cur_qt);
#pragma unroll
            for (int i = 0; i < 8; i++)
#pragma unroll
                for (int j = 0; j < 4; j++) of[i][j] = 0.f;
            lsum0 = lsum1 = 0.f;
            const __nv_bfloat16* qhp = gqh + (size_t)(b * TT + qt * 128) * HH;
            const __nv_bfloat16* qlp = gql + (size_t)(b * TT + qt * 128) * HH;
#pragma unroll
            for (int i = 0; i < 4; i++) {
                int idx = tid + i * 256;
                int r = idx >> 3, c = idx & 7;
                *(uint4*)(smem + OFF_QHI + r * UPITCH + c * 16) =
                    *(const uint4*)(qhp + (size_t)r * HH + c * 8);
                *(uint4*)(smem + OFF_QLO + r * UPITCH + c * 16) =
                    *(const uint4*)(qlp + (size_t)r * HH + c * 8);
            }
            __syncthreads();
            cur_b = b; cur_qt = qt;
        }

        const uint32_t so = sb + OFF_ST + (u & 1) * ST_STRIDE;

        // ---- S = Q K^T (Q fragments loaded per ks) ----
        float sf[8][4];
#pragma unroll
        for (int i = 0; i < 8; i++)
#pragma unroll
            for (int j = 0; j < 4; j++) sf[i][j] = 0.f;

#pragma unroll
        for (int ks = 0; ks < 4; ks++) {
            uint32_t qah[4], qal[4];
            ldsm4(qah, qh_base + ks * 32);
            ldsm4(qal, ql_base + ks * 32);
#pragma unroll
            for (int g = 0; g < 4; g++) {
                uint32_t bh[4], bl[4];
                uint32_t ka = so + (16 * g + b_key) * UPITCH + ks * 32 + b_hsel * 16;
                ldsm4(bh, ka + ST_KHI);
                ldsm4(bl, ka + ST_KLO);
                mma16816(sf[2 * g],     qah, bh[0], bh[1]);
                mma16816(sf[2 * g + 1], qah, bh[2], bh[3]);
                mma16816(sf[2 * g],     qal, bh[0], bh[1]);
                mma16816(sf[2 * g + 1], qal, bh[2], bh[3]);
                mma16816(sf[2 * g],     qah, bl[0], bl[1]);
                mma16816(sf[2 * g + 1], qah, bl[2], bl[3]);
            }
        }

        // ---- fused softmax + PV per 16-column P chunk ----
        const bool needmask = (kc >= 2 * qt);
        const int qrow0 = qt * 128 + wid * 16 + (lane >> 2);
        const int keyb  = kc * 64 + (lane & 3) * 2;
#pragma unroll
        for (int pks = 0; pks < 4; pks++) {
            uint32_t pah[4], pal[4];
#pragma unroll
            for (int h = 0; h < 2; h++) {
                const int n8 = 2 * pks + h;
                int k0 = keyb + n8 * 8;
                float p0 = fast_ex2(sf[n8][0]);
                float p1 = fast_ex2(sf[n8][1]);
                float p2 = fast_ex2(sf[n8][2]);
                float p3 = fast_ex2(sf[n8][3]);
                if (needmask) {
                    if (k0     > qrow0)     p0 = 0.f;
                    if (k0 + 1 > qrow0)     p1 = 0.f;
                    if (k0     > qrow0 + 8) p2 = 0.f;
                    if (k0 + 1 > qrow0 + 8) p3 = 0.f;
                }
                lsum0 += p0 + p1;
                lsum1 += p2 + p3;
                float h0 = bf16rt(p0), h1 = bf16rt(p1);
                float h2 = bf16rt(p2), h3 = bf16rt(p3);
                pah[2 * h]     = packbf2(h0, h1);
                pah[2 * h + 1] = packbf2(h2, h3);
                pal[2 * h]     = packbf2(p0 - h0, p1 - h1);
                pal[2 * h + 1] = packbf2(p2 - h2, p3 - h3);
            }
#pragma unroll
            for (int g = 0; g < 4; g++) {
                uint32_t vh[4], vl[4];
                uint32_t va = so + (16 * g + v_h) * UPITCH + pks * 32 + v_ksel * 16;
                ldsm4(vh, va + ST_VHI);
                ldsm4(vl, va + ST_VLO);
                mma16816(of[2 * g],     pah, vh[0], vh[1]);
                mma16816(of[2 * g + 1], pah, vh[2], vh[3]);
                mma16816(of[2 * g],     pal, vh[0], vh[1]);
                mma16816(of[2 * g + 1], pal, vh[2], vh[3]);
                mma16816(of[2 * g],     pah, vl[0], vl[1]);
                mma16816(of[2 * g + 1], pah, vl[2], vl[3]);
            }
        }

        __syncthreads();
        if (u + 2 < u1) {
            int nb, nqt, nkc;
            decode_unit(u + 2, nb, nqt, nkc);
            prefetch(u & 1, nb, nkc);
        }
        CP_COMMIT();
    }

    flush(cur_b, cur_qt);
}

// ---------------------------------------------------------------------------
// finalize: out = O_acc / l
// ---------------------------------------------------------------------------
__global__ __launch_bounds__(256) void finalize(float* __restrict__ out)
{
    int i = blockIdx.x * 256 + threadIdx.x;
    float4 o = ((const float4*)g_oacc)[i];
    float inv = 1.0f / g_lacc[i >> 4];
    o.x *= inv; o.y *= inv; o.z *= inv; o.w *= inv;
    ((float4*)out)[i] = o;
}

// ---------------------------------------------------------------------------
extern "C" void kernel_launch(void* const* d_in, const int* in_sizes, int n_in,
                              void* d_out, int out_size)
{
    const float* x  = (const float*)d_in[0];
    const float* Wq = (const float*)d_in[1];
    const float* Wk = (const float*)d_in[2];
    const float* Wv = (const float*)d_in[3];
    float* out = (float*)d_out;

    cudaFuncSetAttribute(qkv3_kernel,
                         cudaFuncAttributeMaxDynamicSharedMemorySize, QKV3_SMEM);
    cudaFuncSetAttribute(attn_kernel,
                         cudaFuncAttributeMaxDynamicSharedMemorySize, ATT_SMEM);

    dim3 pw_grid(16, 3);
    prep_w<<<pw_grid, 256>>>(Wq, Wk, Wv);

    qkv3_kernel<<<MM / 128, 256, QKV3_SMEM>>>(x);

    zero_acc<<<MM * HH / 4 / 256, 256>>>();

    attn_kernel<<<ATT_NCTA, 256, ATT_SMEM>>>();

    finalize<<<MM * HH / 4 / 256, 256>>>(out);
}